// round 17
// baseline (speedup 1.0000x reference)
#include <cuda_runtime.h>
#include <cuda_bf16.h>
#include <cstdint>

#define B_SZ 16384
#define IN_D 4096
#define T_SZ 6
#define H_SZ 256
#define TH   1536

// ---------------------------------------------------------------------------
// Scratch (device globals per allocation-guard rules)
// ---------------------------------------------------------------------------
__device__ __nv_bfloat16 g_xb [(size_t)B_SZ * IN_D];           // 128 MB
__device__ __nv_bfloat16 g_w1b[(size_t)TH * IN_D];             // 12.6 MB
__device__ __nv_bfloat16 g_w2b[(size_t)T_SZ * H_SZ * H_SZ];    // 0.75 MB
__device__ __nv_bfloat16 g_h1b[(size_t)B_SZ * TH];             // 50.3 MB
__device__ float g_R[(size_t)B_SZ * T_SZ * 8];                 // 3 MB
__device__ float g_prep[1824];

// ---------------------------------------------------------------------------
// mma / ldmatrix helpers (legacy path — PTX baseline, compiles for sm_103)
// ---------------------------------------------------------------------------
__device__ __forceinline__ void mma_bf16(float* d, const uint32_t* a, const uint32_t* b) {
    asm volatile(
        "mma.sync.aligned.m16n8k16.row.col.f32.bf16.bf16.f32 "
        "{%0,%1,%2,%3}, {%4,%5,%6,%7}, {%8,%9}, {%0,%1,%2,%3};\n"
        : "+f"(d[0]), "+f"(d[1]), "+f"(d[2]), "+f"(d[3])
        : "r"(a[0]), "r"(a[1]), "r"(a[2]), "r"(a[3]), "r"(b[0]), "r"(b[1]));
}
__device__ __forceinline__ void ldsm4(uint32_t* r, uint32_t addr) {
    asm volatile("ldmatrix.sync.aligned.m8n8.x4.shared.b16 {%0,%1,%2,%3}, [%4];"
                 : "=r"(r[0]), "=r"(r[1]), "=r"(r[2]), "=r"(r[3]) : "r"(addr));
}
__device__ __forceinline__ void cpasync16(uint32_t dst, const void* src) {
    asm volatile("cp.async.cg.shared.global [%0], [%1], 16;\n" :: "r"(dst), "l"(src));
}

#define STG_BYTES 49152
#define NSTAGE 4
#define G1_SMEM (NSTAGE*STG_BYTES + 1024)            // 197632
#define G2_SMEM (NSTAGE*STG_BYTES + 2080*4 + 1024)   // 205952

// ===========================================================================
// GEMM1: h1 = relu(x @ W1^T + b1) -> bf16.  M=16384, N=1536, K=4096.
// CTA 256x128, BK=64 (128B rows, SW128 swizzle), 4-stage cp.async,
// 8 warps: 4 over M x 2 over N, warp tile 64x64.
// Inner loop software-pipelines ldmatrix fragments (double buffer over ks).
// ===========================================================================
__global__ void __launch_bounds__(256, 1) gemm1_kernel(
    const __nv_bfloat16* __restrict__ A, const __nv_bfloat16* __restrict__ Bw,
    const float* __restrict__ bias, __nv_bfloat16* __restrict__ C)
{
    extern __shared__ char smraw[];
    uint32_t sm0  = (uint32_t)__cvta_generic_to_shared(smraw);
    uint32_t base = (sm0 + 1023u) & ~1023u;

    const int tid  = threadIdx.x;
    const int lane = tid & 31;
    const int warp = tid >> 5;
    const int wm   = warp & 3;   // 4 warps over M (64 each)
    const int wn   = warp >> 2;  // 2 warps over N (64 each)

    const char* gA = (const char*)(A  + (size_t)blockIdx.y * 256 * IN_D);
    const char* gB = (const char*)(Bw + (size_t)blockIdx.x * 128 * IN_D);
    const float* gbias = bias + blockIdx.x * 128;

    float acc[4][8][4];
#pragma unroll
    for (int i = 0; i < 4; i++)
#pragma unroll
        for (int j = 0; j < 8; j++)
#pragma unroll
            for (int k = 0; k < 4; k++) acc[i][j][k] = 0.f;

    auto load_stage = [&](int stage, int kt) {
        uint32_t sA = base + stage * STG_BYTES;        // A: 256 rows * 128B = 32KB
        uint32_t sB = sA + 32768;                      // B: 128 rows * 128B = 16KB
        const char* gAk = gA + (size_t)kt * 128;
        const char* gBk = gB + (size_t)kt * 128;
#pragma unroll
        for (int i = 0; i < 8; i++) {
            int f = tid + i * 256, r = f >> 3, c8 = f & 7;
            uint32_t off = (uint32_t)(r * 128 + ((c8 ^ (r & 7)) << 4));
            cpasync16(sA + off, gAk + (size_t)r * (IN_D * 2) + c8 * 16);
        }
#pragma unroll
        for (int i = 0; i < 4; i++) {
            int f = tid + i * 256, r = f >> 3, c8 = f & 7;
            uint32_t off = (uint32_t)(r * 128 + ((c8 ^ (r & 7)) << 4));
            cpasync16(sB + off, gBk + (size_t)r * (IN_D * 2) + c8 * 16);
        }
        asm volatile("cp.async.commit_group;\n");
    };

    load_stage(0, 0);
    load_stage(1, 1);
    load_stage(2, 2);

    const int arow = wm * 64 + (lane & 15);
    const int brow = wn * 64 + ((lane >> 4) << 3) + (lane & 7);
    const int KT = IN_D / 64;   // 64

    uint32_t af[2][4][4], bf[2][4][4];

    for (int kt = 0; kt < KT; ++kt) {
        if (KT - kt >= 3)      asm volatile("cp.async.wait_group 2;\n" ::: "memory");
        else if (KT - kt == 2) asm volatile("cp.async.wait_group 1;\n" ::: "memory");
        else                   asm volatile("cp.async.wait_group 0;\n" ::: "memory");
        __syncthreads();
        if (kt + 3 < KT) load_stage((kt + 3) & (NSTAGE - 1), kt + 3);

        uint32_t sA = base + (kt & (NSTAGE - 1)) * STG_BYTES;
        uint32_t sB = sA + 32768;

        // prime ks=0 fragments
        {
            const int ac8 = (lane >> 4);
            const int bc8 = ((lane >> 3) & 1);
#pragma unroll
            for (int mt = 0; mt < 4; mt++)
                ldsm4(af[0][mt], sA + (uint32_t)((arow + mt * 16) * 128 + ((ac8 ^ (arow & 7)) << 4)));
#pragma unroll
            for (int nb = 0; nb < 4; nb++)
                ldsm4(bf[0][nb], sB + (uint32_t)((brow + nb * 16) * 128 + ((bc8 ^ (brow & 7)) << 4)));
        }
#pragma unroll
        for (int ks = 0; ks < 4; ks++) {
            const int cur = ks & 1, nxt = cur ^ 1;
            if (ks < 3) {   // prefetch ks+1 fragments before issuing MMAs
                const int ac8 = (ks + 1) * 2 + (lane >> 4);
                const int bc8 = (ks + 1) * 2 + ((lane >> 3) & 1);
#pragma unroll
                for (int mt = 0; mt < 4; mt++)
                    ldsm4(af[nxt][mt], sA + (uint32_t)((arow + mt * 16) * 128 + ((ac8 ^ (arow & 7)) << 4)));
#pragma unroll
                for (int nb = 0; nb < 4; nb++)
                    ldsm4(bf[nxt][nb], sB + (uint32_t)((brow + nb * 16) * 128 + ((bc8 ^ (brow & 7)) << 4)));
            }
#pragma unroll
            for (int mt = 0; mt < 4; mt++)
#pragma unroll
                for (int nt = 0; nt < 8; nt++)
                    mma_bf16(acc[mt][nt], af[cur][mt], &bf[cur][nt >> 1][(nt & 1) * 2]);
        }
    }

    // Epilogue: + bias, relu, bf16 store
    __nv_bfloat16* crow = C + ((size_t)blockIdx.y * 256) * TH + (size_t)blockIdx.x * 128;
#pragma unroll
    for (int mt = 0; mt < 4; mt++) {
        int r0 = wm * 64 + mt * 16 + (lane >> 2);
#pragma unroll
        for (int nt = 0; nt < 8; nt++) {
            int c0 = wn * 64 + nt * 8 + 2 * (lane & 3);
            float b0 = gbias[c0], b1 = gbias[c0 + 1];
            __nv_bfloat162 p01 = __floats2bfloat162_rn(fmaxf(acc[mt][nt][0] + b0, 0.f),
                                                       fmaxf(acc[mt][nt][1] + b1, 0.f));
            __nv_bfloat162 p23 = __floats2bfloat162_rn(fmaxf(acc[mt][nt][2] + b0, 0.f),
                                                       fmaxf(acc[mt][nt][3] + b1, 0.f));
            *(uint32_t*)(crow + (size_t)r0 * TH + c0)       = *(uint32_t*)&p01;
            *(uint32_t*)(crow + (size_t)(r0 + 8) * TH + c0) = *(uint32_t*)&p23;
        }
    }
}

// ===========================================================================
// GEMM2 + fused reduce, single-shot K: all 4 k-blocks (192KB) loaded upfront
// with max MLP (4 commit groups), then wait_group(3-kt)+sync per kt.
// CTA 128x256, 8 warps: 2 over M x 4 over N. Epilogue parks the h2 tile in
// the dead stage smem (stride 257) and does the 7 dots -> g_R.
// ===========================================================================
#define HS_STRIDE 257

__global__ void __launch_bounds__(256, 1) gemm2_fused_kernel(
    const __nv_bfloat16* __restrict__ A, const __nv_bfloat16* __restrict__ Bw,
    const float* __restrict__ b2, float* __restrict__ R)
{
    extern __shared__ char smraw[];
    uint32_t sm0  = (uint32_t)__cvta_generic_to_shared(smraw);
    uint32_t base = (sm0 + 1023u) & ~1023u;
    char*  smal = smraw + (base - sm0);
    float* hsf  = (float*)smal;
    float* auxf = (float*)(smal + NSTAGE * STG_BYTES);

    const int tid  = threadIdx.x;
    const int lane = tid & 31;
    const int warp = tid >> 5;
    const int wm   = warp & 1;
    const int wn   = warp >> 1;
    const int z    = blockIdx.z;

    const char* gA = (const char*)(A  + (size_t)blockIdx.y * 128 * TH + (size_t)z * 256);
    const char* gB = (const char*)(Bw + (size_t)z * 65536);

    // Issue ALL K loads first (4 groups) for maximum overlap.
#pragma unroll
    for (int kt = 0; kt < 4; kt++) {
        uint32_t sA = base + kt * STG_BYTES;
        uint32_t sB = sA + 16384;
        const char* gAk = gA + (size_t)kt * 128;
        const char* gBk = gB + (size_t)kt * 128;
#pragma unroll
        for (int i = 0; i < 4; i++) {
            int f = tid + i * 256, r = f >> 3, c8 = f & 7;
            uint32_t off = (uint32_t)(r * 128 + ((c8 ^ (r & 7)) << 4));
            cpasync16(sA + off, gAk + (size_t)r * (TH * 2) + c8 * 16);
        }
#pragma unroll
        for (int i = 0; i < 8; i++) {
            int f = tid + i * 256, r = f >> 3, c8 = f & 7;
            uint32_t off = (uint32_t)(r * 128 + ((c8 ^ (r & 7)) << 4));
            cpasync16(sB + off, gBk + (size_t)r * (H_SZ * 2) + c8 * 16);
        }
        asm volatile("cp.async.commit_group;\n");
    }

    for (int i = tid; i < 1800; i += 256) auxf[i] = g_prep[i];
    for (int i = tid; i < 256;  i += 256) auxf[1800 + i] = b2[z * 256 + i];

    float acc[4][8][4];
#pragma unroll
    for (int i = 0; i < 4; i++)
#pragma unroll
        for (int j = 0; j < 8; j++)
#pragma unroll
            for (int k = 0; k < 4; k++) acc[i][j][k] = 0.f;

    const int arow = wm * 64 + (lane & 15);
    const int brow = wn * 64 + ((lane >> 4) << 3) + (lane & 7);

#pragma unroll
    for (int kt = 0; kt < 4; kt++) {
        if (kt == 0)      asm volatile("cp.async.wait_group 3;\n" ::: "memory");
        else if (kt == 1) asm volatile("cp.async.wait_group 2;\n" ::: "memory");
        else if (kt == 2) asm volatile("cp.async.wait_group 1;\n" ::: "memory");
        else              asm volatile("cp.async.wait_group 0;\n" ::: "memory");
        __syncthreads();

        uint32_t sA = base + kt * STG_BYTES;
        uint32_t sB = sA + 16384;
#pragma unroll
        for (int ks = 0; ks < 4; ks++) {
            uint32_t af[4][4], bf[4][4];
            const int ac8 = ks * 2 + (lane >> 4);
            const int bc8 = ks * 2 + ((lane >> 3) & 1);
#pragma unroll
            for (int mt = 0; mt < 4; mt++)
                ldsm4(af[mt], sA + (uint32_t)((arow + mt * 16) * 128 + ((ac8 ^ (arow & 7)) << 4)));
#pragma unroll
            for (int nb = 0; nb < 4; nb++)
                ldsm4(bf[nb], sB + (uint32_t)((brow + nb * 16) * 128 + ((bc8 ^ (brow & 7)) << 4)));
#pragma unroll
            for (int mt = 0; mt < 4; mt++)
#pragma unroll
                for (int nt = 0; nt < 8; nt++)
                    mma_bf16(acc[mt][nt], af[mt], &bf[nt >> 1][(nt & 1) * 2]);
        }
    }
    __syncthreads();   // stages dead; safe to overwrite with h2 tile

    // relu(acc + bias) -> smem tile (row stride 257 floats)
#pragma unroll
    for (int mt = 0; mt < 4; mt++) {
        int r0 = wm * 64 + mt * 16 + (lane >> 2);
#pragma unroll
        for (int nt = 0; nt < 8; nt++) {
            int c0 = wn * 64 + nt * 8 + 2 * (lane & 3);
            float b0 = auxf[1800 + c0], b1 = auxf[1800 + c0 + 1];
            hsf[r0 * HS_STRIDE + c0]           = fmaxf(acc[mt][nt][0] + b0, 0.f);
            hsf[r0 * HS_STRIDE + c0 + 1]       = fmaxf(acc[mt][nt][1] + b1, 0.f);
            hsf[(r0 + 8) * HS_STRIDE + c0]     = fmaxf(acc[mt][nt][2] + b0, 0.f);
            hsf[(r0 + 8) * HS_STRIDE + c0 + 1] = fmaxf(acc[mt][nt][3] + b1, 0.f);
        }
    }
    __syncthreads();

    // 7 dots per row; 2 threads per row (128 h each), combine via shfl
    const int row = tid >> 1;
    const int h0  = (tid & 1) * 128;
    float s[7] = {0, 0, 0, 0, 0, 0, 0};
#pragma unroll 4
    for (int h = 0; h < 128; h++) {
        const int hh = h0 + h;
        float v = hsf[row * HS_STRIDE + hh];
#pragma unroll
        for (int q = 0; q < 6; q++) s[q] += v * auxf[q * 256 + hh];
        s[6] += v * auxf[1536 + hh];
    }
#pragma unroll
    for (int t = 0; t < 7; t++) s[t] += __shfl_xor_sync(0xffffffffu, s[t], 1);
    if ((tid & 1) == 0) {
        const size_t m = (size_t)blockIdx.y * 128 + row;
        float* o = R + (m * T_SZ + z) * 8;
#pragma unroll
        for (int q = 0; q < 6; q++) o[q] = (s[q] + auxf[1792 + q]) * 0.0625f; // /sqrt(256)
        o[6] = s[6] + auxf[1798];
    }
}

// ---------------------------------------------------------------------------
// fp32 -> bf16 convert (vectorized, grid-stride)
// ---------------------------------------------------------------------------
__global__ void convert_kernel(const float4* __restrict__ src, uint2* __restrict__ dst, int n4)
{
    int i = blockIdx.x * blockDim.x + threadIdx.x;
    const int stride = gridDim.x * blockDim.x;
    for (; i < n4; i += stride) {
        float4 v = src[i];
        __nv_bfloat162 a = __floats2bfloat162_rn(v.x, v.y);
        __nv_bfloat162 b = __floats2bfloat162_rn(v.z, v.w);
        uint2 o;
        o.x = *(uint32_t*)&a;
        o.y = *(uint32_t*)&b;
        dst[i] = o;
    }
}

// ---------------------------------------------------------------------------
// Prep (7 blocks; MLP-unrolled o-loop with 4 accumulators)
// ---------------------------------------------------------------------------
__global__ void __launch_bounds__(256) prep_kernel(
    const float* __restrict__ tq, const float* __restrict__ keyW,
    const float* __restrict__ keyb, const float* __restrict__ valW,
    const float* __restrict__ valb)
{
    __shared__ float tqs[256];
    __shared__ float red[256];
    const int q = blockIdx.x;
    const int h = threadIdx.x;

    if (q < 6) {
        tqs[h] = tq[q * 256 + h];
        red[h] = tqs[h] * keyb[h];
        __syncthreads();
        float a0 = 0.f, a1 = 0.f, a2 = 0.f, a3 = 0.f;
#pragma unroll 2
        for (int o = 0; o < 256; o += 8) {
            a0 += tqs[o + 0] * keyW[(o + 0) * 256 + h];
            a1 += tqs[o + 1] * keyW[(o + 1) * 256 + h];
            a2 += tqs[o + 2] * keyW[(o + 2) * 256 + h];
            a3 += tqs[o + 3] * keyW[(o + 3) * 256 + h];
            a0 += tqs[o + 4] * keyW[(o + 4) * 256 + h];
            a1 += tqs[o + 5] * keyW[(o + 5) * 256 + h];
            a2 += tqs[o + 6] * keyW[(o + 6) * 256 + h];
            a3 += tqs[o + 7] * keyW[(o + 7) * 256 + h];
        }
        g_prep[q * 256 + h] = (a0 + a1) + (a2 + a3);
        for (int sft = 128; sft > 0; sft >>= 1) {
            if (h < sft) red[h] += red[h + sft];
            __syncthreads();
        }
        if (h == 0) g_prep[1792 + q] = red[0];
    } else {
        red[h] = valb[h];
        __syncthreads();
        float a0 = 0.f, a1 = 0.f, a2 = 0.f, a3 = 0.f;
#pragma unroll 2
        for (int o = 0; o < 256; o += 8) {
            a0 += valW[(o + 0) * 256 + h];
            a1 += valW[(o + 1) * 256 + h];
            a2 += valW[(o + 2) * 256 + h];
            a3 += valW[(o + 3) * 256 + h];
            a0 += valW[(o + 4) * 256 + h];
            a1 += valW[(o + 5) * 256 + h];
            a2 += valW[(o + 6) * 256 + h];
            a3 += valW[(o + 7) * 256 + h];
        }
        g_prep[1536 + h] = ((a0 + a1) + (a2 + a3)) * (1.0f / 256.0f);
        for (int sft = 128; sft > 0; sft >>= 1) {
            if (h < sft) red[h] += red[h + sft];
            __syncthreads();
        }
        if (h == 0) g_prep[1798] = red[0] * (1.0f / 256.0f);
    }
}

// ---------------------------------------------------------------------------
// Final: per b, 6x6 softmax(I + 0.1*logits/m) @ vmean, sigmoid, clip.
// ---------------------------------------------------------------------------
__global__ void final_kernel(float* __restrict__ out, const float* __restrict__ biasPtr)
{
    int b = blockIdx.x * 256 + threadIdx.x;
    float lg[6][6], vm[6];
#pragma unroll
    for (int k = 0; k < 6; k++) {
        const float* rk = g_R + ((size_t)b * 6 + k) * 8;
#pragma unroll
        for (int q = 0; q < 6; q++) lg[q][k] = rk[q];
        vm[k] = rk[6];
    }
    float bv = *biasPtr;
#pragma unroll
    for (int q = 0; q < 6; q++) {
        float m = lg[q][0];
#pragma unroll
        for (int k = 1; k < 6; k++) m = fmaxf(m, lg[q][k]);
        m += 1e-8f;
        float s[6];
        float mx = -1e30f;
#pragma unroll
        for (int k = 0; k < 6; k++) {
            s[k] = ((k == q) ? 1.0f : 0.0f) + 0.1f * (lg[q][k] / m);
            mx = fmaxf(mx, s[k]);
        }
        float den = 0.f, num = 0.f;
#pragma unroll
        for (int k = 0; k < 6; k++) {
            float e = expf(s[k] - mx);
            den += e;
            num += e * vm[k];
        }
        float y = num / den - bv;
        float p = 1.0f / (1.0f + expf(-y));
        p = fminf(fmaxf(p, 1e-7f), 1.0f - 1e-7f);
        out[(size_t)b * 6 + q] = p;
    }
}

// ---------------------------------------------------------------------------
// Launch
// ---------------------------------------------------------------------------
extern "C" void kernel_launch(void* const* d_in, const int* in_sizes, int n_in,
                              void* d_out, int out_size)
{
    const float* x    = (const float*)d_in[0];
    const float* W1   = (const float*)d_in[1];   // [1536, 4096]
    const float* b1   = (const float*)d_in[2];
    const float* W2   = (const float*)d_in[3];   // [6, 256, 256]
    const float* b2   = (const float*)d_in[4];
    const float* tq   = (const float*)d_in[5];
    const float* keyW = (const float*)d_in[6];
    const float* keyb = (const float*)d_in[7];
    const float* valW = (const float*)d_in[8];
    const float* valb = (const float*)d_in[9];
    const float* bias = (const float*)d_in[10];
    float* out = (float*)d_out;

    __nv_bfloat16 *xb = nullptr, *w1b = nullptr, *w2b = nullptr, *h1b = nullptr;
    float* Rp = nullptr;
    cudaGetSymbolAddress((void**)&xb,  g_xb);
    cudaGetSymbolAddress((void**)&w1b, g_w1b);
    cudaGetSymbolAddress((void**)&w2b, g_w2b);
    cudaGetSymbolAddress((void**)&h1b, g_h1b);
    cudaGetSymbolAddress((void**)&Rp,  g_R);

    cudaFuncSetAttribute(gemm1_kernel, cudaFuncAttributeMaxDynamicSharedMemorySize, G1_SMEM);
    cudaFuncSetAttribute(gemm2_fused_kernel, cudaFuncAttributeMaxDynamicSharedMemorySize, G2_SMEM);

    convert_kernel<<<4096, 256>>>((const float4*)x,  (uint2*)xb,  B_SZ * IN_D / 4);
    convert_kernel<<<1024, 256>>>((const float4*)W1, (uint2*)w1b, TH * IN_D / 4);
    convert_kernel<<<96,   256>>>((const float4*)W2, (uint2*)w2b, T_SZ * H_SZ * H_SZ / 4);
    prep_kernel<<<7, 256>>>(tq, keyW, keyb, valW, valb);

    // GEMM1: M=16384 (64 tiles of 256), N=1536 (12 tiles of 128), K=4096
    gemm1_kernel<<<dim3(12, 64, 1), 256, G1_SMEM>>>(xb, w1b, b1, h1b);

    // GEMM2 + fused reduce: per task z, tiles of 128 rows x full 256 cols
    gemm2_fused_kernel<<<dim3(1, 128, T_SZ), 256, G2_SMEM>>>(h1b, w2b, b2, Rp);

    final_kernel<<<B_SZ / 256, 256>>>(out, bias);
}